// round 1
// baseline (speedup 1.0000x reference)
#include <cuda_runtime.h>

#define NTOK 4096
#define HID  1024
#define NEXP 64
#define TOPK 8
#define IDIM 768
#define N1   1536
#define FLAT (NTOK*TOPK)     // 32768
#define BM   128
#define MPAD 40960           // 32768 + 64*127 rounded up
#define MAXTILES 320         // <= 32768/128 + 64

// ---------------- scratch (static device globals; no allocation) ----------------
static __device__ float g_g1[(size_t)MPAD * N1];     // GEMM1 output [MPAD, 1536]
static __device__ float g_inter[(size_t)MPAD * IDIM];// SwiGLU output [MPAD, 768]
static __device__ float g_y2[(size_t)MPAD * HID];    // GEMM2 output [MPAD, 1024]
static __device__ float g_topkw[FLAT];
static __device__ int   g_flatexp[FLAT];
static __device__ int   g_invperm[FLAT];
static __device__ int   g_rowtok[MPAD];
static __device__ int   g_counts[NEXP];
static __device__ int   g_ctr[NEXP];
static __device__ int   g_offpad[NEXP];
static __device__ int   g_segend[NEXP];
static __device__ int   g_tile_e[MAXTILES];
static __device__ int   g_tile_r0[MAXTILES];
static __device__ int   g_ntiles;

// ---------------- init ----------------
__global__ void init_kernel() {
    int i = threadIdx.x;
    if (i < NEXP) { g_counts[i] = 0; g_ctr[i] = 0; }
}

// ---------------- router: logits -> top8 of softmax -> renormalized weights ----------------
__global__ void router_kernel(const float* __restrict__ x, const float* __restrict__ gate) {
    __shared__ float xs[HID];
    __shared__ float lg[NEXP];
    int t = blockIdx.x;
    int tid = threadIdx.x;  // 64 threads

    const float4* xsrc = (const float4*)(x + (size_t)t * HID);
    for (int i = tid; i < HID / 4; i += 64) ((float4*)xs)[i] = xsrc[i];
    __syncthreads();

    const float* g = gate + (size_t)tid * HID;
    float s = 0.f;
    #pragma unroll 8
    for (int k = 0; k < HID; k += 4) {
        float4 gv = *(const float4*)(g + k);
        s += xs[k] * gv.x + xs[k+1] * gv.y + xs[k+2] * gv.z + xs[k+3] * gv.w;
    }
    lg[tid] = s;
    __syncthreads();

    if (tid == 0) {
        float mx = lg[0];
        #pragma unroll
        for (int e = 1; e < NEXP; e++) mx = fmaxf(mx, lg[e]);
        unsigned long long taken = 0ull;
        int sel[TOPK]; float wv[TOPK]; float wsum = 0.f;
        for (int k = 0; k < TOPK; k++) {
            int best = 0; float bv = -1e30f;
            for (int e = 0; e < NEXP; e++) {
                float v = lg[e];
                if (!((taken >> e) & 1ull) && v > bv) { bv = v; best = e; }
            }
            taken |= 1ull << best;
            sel[k] = best;
            float w = expf(lg[best] - mx);   // softmax denominator cancels after renorm
            wv[k] = w; wsum += w;
            atomicAdd(&g_counts[best], 1);
        }
        float inv = 1.f / wsum;
        for (int k = 0; k < TOPK; k++) {
            g_topkw[t * TOPK + k]  = wv[k] * inv;
            g_flatexp[t * TOPK + k] = sel[k];
        }
    }
}

// ---------------- tile metadata: padded offsets + tile table ----------------
__global__ void meta_kernel() {
    if (threadIdx.x != 0) return;
    int nt = 0, cum = 0;
    for (int e = 0; e < NEXP; e++) {
        g_offpad[e] = cum;
        int c = g_counts[e];
        g_segend[e] = cum + c;
        int t = (c + BM - 1) / BM;
        for (int j = 0; j < t; j++) { g_tile_e[nt] = e; g_tile_r0[nt] = cum + j * BM; nt++; }
        cum += t * BM;
    }
    g_ntiles = nt;
}

__global__ void fill_kernel() {
    int i = blockIdx.x * 256 + threadIdx.x;
    if (i < MPAD) g_rowtok[i] = -1;
}

// counting-sort scatter (order within expert is irrelevant to the final output)
__global__ void scatter_kernel() {
    int i = blockIdx.x * 256 + threadIdx.x;
    if (i >= FLAT) return;
    int e = g_flatexp[i];
    int dest = g_offpad[e] + atomicAdd(&g_ctr[e], 1);
    g_rowtok[dest] = i >> 3;     // token id
    g_invperm[i] = dest;
}

// ---------------- grouped GEMM: C[m,n] = sum_k A[m,k] * W[e,n,k] ----------------
union F4U { float4 f; unsigned long long u[2]; };
union UF2 { unsigned long long u; float2 f; };

template<int NCOLS, int KDIM, bool GATHER>
__global__ void __launch_bounds__(256, 2) gemm_kernel(const float* __restrict__ Ain,
                                                      const float* __restrict__ W) {
    int tile = blockIdx.x;
    if (tile >= g_ntiles) return;
    int e    = g_tile_e[tile];
    int row0 = g_tile_r0[tile];
    int segend = g_segend[e];
    int n0 = blockIdx.y * 128;

    const float* A = GATHER ? Ain : (const float*)g_inter;
    float*       C = GATHER ? g_g1 : g_y2;
    const float* Bp = W + (size_t)e * ((size_t)NCOLS * KDIM);

    __shared__ float As[16][128];
    __shared__ float Bs2[16][256];   // B duplicated into f32x2 pairs

    int tid = threadIdx.x;
    int lr = tid >> 1;               // 0..127 (tile row for A, tile col-row for B)
    int lk = (tid & 1) << 3;         // 0 or 8

    int arow;
    if (GATHER) {
        int m = row0 + lr;
        arow = (m < segend) ? g_rowtok[m] : -1;
    } else {
        arow = row0 + lr;            // padding rows of g_inter are zeroed by swiglu
    }
    const float* Aptr = (arow >= 0) ? (A + (size_t)arow * KDIM + lk) : (const float*)0;
    const float* Bptr = Bp + (size_t)(n0 + lr) * KDIM + lk;

    int tr8  = (tid >> 4) << 3;      // output row base within tile
    int tc   = tid & 15;
    int tc16 = tc << 4;

    unsigned long long acc[4][8];
    #pragma unroll
    for (int i = 0; i < 4; i++)
        #pragma unroll
        for (int j = 0; j < 8; j++) acc[i][j] = 0ull;

    #pragma unroll 1
    for (int k0 = 0; k0 < KDIM; k0 += 16) {
        float4 av0, av1, bv0, bv1;
        if (Aptr) {
            av0 = *(const float4*)(Aptr + k0);
            av1 = *(const float4*)(Aptr + k0 + 4);
        } else {
            av0 = make_float4(0.f, 0.f, 0.f, 0.f); av1 = av0;
        }
        bv0 = *(const float4*)(Bptr + k0);
        bv1 = *(const float4*)(Bptr + k0 + 4);

        __syncthreads();   // previous compute done before overwrite
        As[lk+0][lr] = av0.x; As[lk+1][lr] = av0.y; As[lk+2][lr] = av0.z; As[lk+3][lr] = av0.w;
        As[lk+4][lr] = av1.x; As[lk+5][lr] = av1.y; As[lk+6][lr] = av1.z; As[lk+7][lr] = av1.w;
        int lr2 = lr << 1;
        *(float2*)&Bs2[lk+0][lr2] = make_float2(bv0.x, bv0.x);
        *(float2*)&Bs2[lk+1][lr2] = make_float2(bv0.y, bv0.y);
        *(float2*)&Bs2[lk+2][lr2] = make_float2(bv0.z, bv0.z);
        *(float2*)&Bs2[lk+3][lr2] = make_float2(bv0.w, bv0.w);
        *(float2*)&Bs2[lk+4][lr2] = make_float2(bv1.x, bv1.x);
        *(float2*)&Bs2[lk+5][lr2] = make_float2(bv1.y, bv1.y);
        *(float2*)&Bs2[lk+6][lr2] = make_float2(bv1.z, bv1.z);
        *(float2*)&Bs2[lk+7][lr2] = make_float2(bv1.w, bv1.w);
        __syncthreads();

        #pragma unroll
        for (int kk = 0; kk < 16; kk++) {
            F4U a0, a1, q0, q1, q2, q3;
            a0.f = *(const float4*)&As[kk][tr8];
            a1.f = *(const float4*)&As[kk][tr8 + 4];
            q0.f = *(const float4*)&Bs2[kk][tc16];
            q1.f = *(const float4*)&Bs2[kk][tc16 + 4];
            q2.f = *(const float4*)&Bs2[kk][tc16 + 8];
            q3.f = *(const float4*)&Bs2[kk][tc16 + 12];
            unsigned long long av[4] = {a0.u[0], a0.u[1], a1.u[0], a1.u[1]};
            unsigned long long bvv[8] = {q0.u[0], q0.u[1], q1.u[0], q1.u[1],
                                         q2.u[0], q2.u[1], q3.u[0], q3.u[1]};
            #pragma unroll
            for (int i = 0; i < 4; i++)
                #pragma unroll
                for (int j = 0; j < 8; j++)
                    asm("fma.rn.f32x2 %0, %1, %2, %0;"
                        : "+l"(acc[i][j]) : "l"(av[i]), "l"(bvv[j]));
        }
    }

    // epilogue: unpack f32x2 pairs (rows 2i2 / 2i2+1)
    #pragma unroll
    for (int r = 0; r < 8; r++) {
        int m = row0 + tr8 + r;
        if (GATHER && m >= segend) continue;
        int i2 = r >> 1, p = r & 1;
        float o[8];
        #pragma unroll
        for (int j = 0; j < 8; j++) { UF2 u; u.u = acc[i2][j]; o[j] = p ? u.f.y : u.f.x; }
        float* cp = C + (size_t)m * NCOLS + n0 + (tc << 3);
        *(float4*)cp       = make_float4(o[0], o[1], o[2], o[3]);
        *(float4*)(cp + 4) = make_float4(o[4], o[5], o[6], o[7]);
    }
}

// ---------------- SwiGLU: inter = silu(g1[:, :768]) * g1[:, 768:] ----------------
__global__ void swiglu_kernel() {
    int gid = blockIdx.x * 256 + threadIdx.x;   // over MPAD * 192 float4s
    if (gid >= MPAD * (IDIM / 4)) return;
    int m = gid / (IDIM / 4);
    int c = gid % (IDIM / 4);
    float4 o;
    if (g_rowtok[m] < 0) {
        o = make_float4(0.f, 0.f, 0.f, 0.f);   // zero padding rows for GEMM2
    } else {
        float4 gv = *(const float4*)&g_g1[(size_t)m * N1 + c * 4];
        float4 uv = *(const float4*)&g_g1[(size_t)m * N1 + IDIM + c * 4];
        o.x = gv.x / (1.f + expf(-gv.x)) * uv.x;
        o.y = gv.y / (1.f + expf(-gv.y)) * uv.y;
        o.z = gv.z / (1.f + expf(-gv.z)) * uv.z;
        o.w = gv.w / (1.f + expf(-gv.w)) * uv.w;
    }
    *(float4*)&g_inter[(size_t)m * IDIM + c * 4] = o;
}

// ---------------- combine: out[t] = sum_k w[t,k] * y2[invperm[8t+k]] ----------------
__global__ void combine_kernel(float* __restrict__ out) {
    __shared__ float w[TOPK];
    __shared__ int rows[TOPK];
    int t = blockIdx.x;
    int tid = threadIdx.x;   // 256 threads, one float4 each (1024/4)
    if (tid < TOPK) {
        w[tid] = g_topkw[t * TOPK + tid];
        rows[tid] = g_invperm[t * TOPK + tid];
    }
    __syncthreads();
    float4 acc = make_float4(0.f, 0.f, 0.f, 0.f);
    #pragma unroll
    for (int k = 0; k < TOPK; k++) {
        const float4 v = *(const float4*)&g_y2[(size_t)rows[k] * HID + (tid << 2)];
        float wk = w[k];
        acc.x += wk * v.x; acc.y += wk * v.y; acc.z += wk * v.z; acc.w += wk * v.w;
    }
    *(float4*)(out + (size_t)t * HID + (tid << 2)) = acc;
}

// ---------------- launch ----------------
extern "C" void kernel_launch(void* const* d_in, const int* in_sizes, int n_in,
                              void* d_out, int out_size) {
    const float* x    = (const float*)d_in[0];   // [2,2048,1024]
    const float* gate = (const float*)d_in[1];   // [64,1024]
    const float* gup  = (const float*)d_in[2];   // [64,1536,1024]
    const float* dwn  = (const float*)d_in[3];   // [64,1024,768]
    float* out = (float*)d_out;

    init_kernel<<<1, 64>>>();
    router_kernel<<<NTOK, 64>>>(x, gate);
    meta_kernel<<<1, 1>>>();
    fill_kernel<<<(MPAD + 255) / 256, 256>>>();
    scatter_kernel<<<(FLAT + 255) / 256, 256>>>();
    gemm_kernel<N1, HID, true><<<dim3(MAXTILES, N1 / 128), 256>>>(x, gup);
    swiglu_kernel<<<(MPAD * (IDIM / 4) + 255) / 256, 256>>>();
    gemm_kernel<HID, IDIM, false><<<dim3(MAXTILES, HID / 128), 256>>>(nullptr, dwn);
    combine_kernel<<<NTOK, 256>>>(out);
}

// round 4
// speedup vs baseline: 5.7060x; 5.7060x over previous
#include <cuda_runtime.h>
#include <cuda_bf16.h>
#include <cstdint>

#define NTOK 4096
#define HID  1024
#define NEXP 64
#define TOPK 8
#define IDIM 768
#define FLAT (NTOK*TOPK)
#define BM   128
#define MPAD 40960
#define MAXTILES 320

// ---------------- scratch ----------------
static __device__ float g_inter[(size_t)MPAD * IDIM];
static __device__ float g_y2[(size_t)MPAD * HID];
static __device__ float g_topkw[FLAT];
static __device__ int   g_flatexp[FLAT];
static __device__ int   g_invperm[FLAT];
static __device__ int   g_rowtok[MPAD];
static __device__ int   g_counts[NEXP];
static __device__ int   g_ctr[NEXP];
static __device__ int   g_offpad[NEXP];
static __device__ int   g_tile_e[MAXTILES];
static __device__ int   g_tile_r0[MAXTILES];
static __device__ int   g_ntiles;

// ---------------- helpers ----------------
__device__ __forceinline__ uint32_t smem_u32(const void* p) {
    uint32_t a;
    asm("{ .reg .u64 t; cvta.to.shared.u64 t, %1; cvt.u32.u64 %0, t; }" : "=r"(a) : "l"(p));
    return a;
}
#define STS128(a, v) \
    asm volatile("st.shared.v4.b32 [%0], {%1, %2, %3, %4};" \
        :: "r"(a), "r"((v).x), "r"((v).y), "r"((v).z), "r"((v).w) : "memory")

__device__ __forceinline__ void ldsm_x4(uint32_t (&r)[4], uint32_t addr) {
    asm volatile("ldmatrix.sync.aligned.m8n8.x4.shared.b16 {%0,%1,%2,%3}, [%4];"
        : "=r"(r[0]), "=r"(r[1]), "=r"(r[2]), "=r"(r[3]) : "r"(addr));
}
__device__ __forceinline__ void mma16816(float (&d)[4], const uint32_t (&a)[4], const uint32_t (&b)[2]) {
    asm volatile("mma.sync.aligned.m16n8k16.row.col.f32.bf16.bf16.f32 "
        "{%0,%1,%2,%3}, {%4,%5,%6,%7}, {%8,%9}, {%0,%1,%2,%3};"
        : "+f"(d[0]), "+f"(d[1]), "+f"(d[2]), "+f"(d[3])
        : "r"(a[0]), "r"(a[1]), "r"(a[2]), "r"(a[3]), "r"(b[0]), "r"(b[1]));
}

// fp32x8 -> bf16 hi/lo split
__device__ __forceinline__ void cvt8(const float4 f0, const float4 f1, uint4& H, uint4& L) {
    __nv_bfloat162 h;
    h = __float22bfloat162_rn(make_float2(f0.x, f0.y)); uint32_t u0 = *(uint32_t*)&h;
    h = __float22bfloat162_rn(make_float2(f0.z, f0.w)); uint32_t u1 = *(uint32_t*)&h;
    h = __float22bfloat162_rn(make_float2(f1.x, f1.y)); uint32_t u2 = *(uint32_t*)&h;
    h = __float22bfloat162_rn(make_float2(f1.z, f1.w)); uint32_t u3 = *(uint32_t*)&h;
    H = make_uint4(u0, u1, u2, u3);
    float l0 = f0.x - __uint_as_float(u0 << 16);
    float l1 = f0.y - __uint_as_float(u0 & 0xFFFF0000u);
    float l2 = f0.z - __uint_as_float(u1 << 16);
    float l3 = f0.w - __uint_as_float(u1 & 0xFFFF0000u);
    float l4 = f1.x - __uint_as_float(u2 << 16);
    float l5 = f1.y - __uint_as_float(u2 & 0xFFFF0000u);
    float l6 = f1.z - __uint_as_float(u3 << 16);
    float l7 = f1.w - __uint_as_float(u3 & 0xFFFF0000u);
    h = __float22bfloat162_rn(make_float2(l0, l1)); uint32_t v0 = *(uint32_t*)&h;
    h = __float22bfloat162_rn(make_float2(l2, l3)); uint32_t v1 = *(uint32_t*)&h;
    h = __float22bfloat162_rn(make_float2(l4, l5)); uint32_t v2 = *(uint32_t*)&h;
    h = __float22bfloat162_rn(make_float2(l6, l7)); uint32_t v3 = *(uint32_t*)&h;
    L = make_uint4(v0, v1, v2, v3);
}

// swizzled byte offset within a [128 rows][32 bf16] tile (64B rows, 16B chunks)
__device__ __forceinline__ uint32_t swz(int row, int chunk) {
    return (uint32_t)(row * 64 + ((chunk ^ ((row >> 1) & 3)) << 4));
}

// ---------------- small kernels ----------------
__global__ void init_kernel() {
    int i = threadIdx.x;
    if (i < NEXP) { g_counts[i] = 0; g_ctr[i] = 0; }
}

#define RT 8
__global__ void router_kernel(const float* __restrict__ x, const float* __restrict__ gate) {
    __shared__ float xs[RT][HID];
    __shared__ float lg[RT][NEXP];
    int t0 = blockIdx.x * RT;
    int tid = threadIdx.x;  // 256
    const float4* xsrc = (const float4*)(x + (size_t)t0 * HID);
    for (int i = tid; i < RT * HID / 4; i += 256) ((float4*)&xs[0][0])[i] = xsrc[i];
    __syncthreads();
    int tt = tid >> 5, lane = tid & 31;
    #pragma unroll
    for (int g = 0; g < 2; g++) {
        int e = g * 32 + lane;
        const float* gp = gate + (size_t)e * HID;
        float s = 0.f;
        #pragma unroll 4
        for (int k = 0; k < HID; k += 4) {
            float4 gv = *(const float4*)(gp + k);
            s += xs[tt][k] * gv.x + xs[tt][k+1] * gv.y + xs[tt][k+2] * gv.z + xs[tt][k+3] * gv.w;
        }
        lg[tt][e] = s;
    }
    __syncthreads();
    if (tid < RT) {
        int t = t0 + tid;
        float mx = lg[tid][0];
        #pragma unroll
        for (int e = 1; e < NEXP; e++) mx = fmaxf(mx, lg[tid][e]);
        unsigned long long taken = 0ull;
        float wsum = 0.f;
        int sel[TOPK]; float wv[TOPK];
        for (int k = 0; k < TOPK; k++) {
            int best = 0; float bv = -1e30f;
            for (int e = 0; e < NEXP; e++) {
                float v = lg[tid][e];
                if (!((taken >> e) & 1ull) && v > bv) { bv = v; best = e; }
            }
            taken |= 1ull << best;
            sel[k] = best;
            float w = expf(lg[tid][best] - mx);
            wv[k] = w; wsum += w;
            atomicAdd(&g_counts[best], 1);
        }
        float inv = 1.f / wsum;
        for (int k = 0; k < TOPK; k++) {
            g_topkw[t * TOPK + k]   = wv[k] * inv;
            g_flatexp[t * TOPK + k] = sel[k];
        }
    }
}

__global__ void meta_kernel() {
    if (threadIdx.x != 0) return;
    int nt = 0, cum = 0;
    for (int e = 0; e < NEXP; e++) {
        g_offpad[e] = cum;
        int c = g_counts[e];
        int t = (c + BM - 1) / BM;
        for (int j = 0; j < t; j++) { g_tile_e[nt] = e; g_tile_r0[nt] = cum + j * BM; nt++; }
        cum += t * BM;
    }
    g_ntiles = nt;
}

__global__ void fill_kernel() {
    int i = blockIdx.x * 256 + threadIdx.x;
    if (i < MPAD) g_rowtok[i] = -1;
}

__global__ void scatter_kernel() {
    int i = blockIdx.x * 256 + threadIdx.x;
    if (i >= FLAT) return;
    int e = g_flatexp[i];
    int dest = g_offpad[e] + atomicAdd(&g_ctr[e], 1);
    g_rowtok[dest] = i >> 3;
    g_invperm[i] = dest;
}

// ---------------- grouped GEMM via mma.sync bf16 3-term split ----------------
// CTA: 256 thr = 8 warps (2x4), tile M=128 x N=128, warp tile 64x32, KC=32.
// B is stored [n][k] (k contiguous) -> the NON-trans ldmatrix fragment of the
// stored matrix IS the mma B fragment (two consecutive k at fixed n).
// FUSED (GEMM1): B rows 0-63 = gate[nb*64+r], rows 64-127 = up[nb*64+(r-64)];
//                epilogue computes silu(gate)*up -> g_inter (64 output cols/CTA).
// else (GEMM2):  B rows = down[nb*128+r]; epilogue -> g_y2.

template<bool FUSED>
__global__ void __launch_bounds__(256, 1) moe_gemm(const float* __restrict__ Ain,
                                                   const float* __restrict__ W) {
    constexpr int KDIM = FUSED ? HID : IDIM;   // 1024 / 768
    constexpr int NK   = KDIM / 32;            // 32 / 24
    int tile = blockIdx.x;
    if (tile >= g_ntiles) return;
    int e = g_tile_e[tile], row0 = g_tile_r0[tile], nb = blockIdx.y;

    __shared__ __align__(128) uint16_t sT[4 * 128 * 32];   // 32KB: Ahi|Alo|Bhi|Blo
    uint32_t sb = smem_u32(sT);
    const uint32_t SA_HI = sb, SA_LO = sb + 8192, SB_HI = sb + 16384, SB_LO = sb + 24576;

    int tid = threadIdx.x, lane = tid & 31, wid = tid >> 5;
    int wm = wid >> 2, wn = wid & 3;

    // -------- load-slot mapping: row = tid/4, chunk = tid%4 (two 64-row groups)
    int rA0 = tid >> 2, rA1 = rA0 + 64, ch = tid & 3;
    uint32_t off0 = swz(rA0, ch);
    uint32_t off1 = swz(rA1, ch);

    const float* aptr0; const float* aptr1;
    if (FUSED) {
        int t0 = g_rowtok[row0 + rA0], t1 = g_rowtok[row0 + rA1];
        aptr0 = (t0 >= 0) ? Ain + (size_t)t0 * HID + ch * 8 : nullptr;
        aptr1 = (t1 >= 0) ? Ain + (size_t)t1 * HID + ch * 8 : nullptr;
    } else {
        aptr0 = g_inter + (size_t)(row0 + rA0) * IDIM + ch * 8;
        aptr1 = g_inter + (size_t)(row0 + rA1) * IDIM + ch * 8;
    }
    const float* Wb = W + (size_t)e * (size_t)(FUSED ? 2 * IDIM : HID) * KDIM;
    int wr0 = FUSED ? (nb * 64 + rA0) : (nb * 128 + rA0);           // rA0 in 0..63
    int wr1 = FUSED ? (IDIM + nb * 64 + (rA1 - 64)) : (nb * 128 + rA1);
    const float* bptr0 = Wb + (size_t)wr0 * KDIM + ch * 8;
    const float* bptr1 = Wb + (size_t)wr1 * KDIM + ch * 8;

    // -------- fragment addressing (per lane, constant parts)
    int arow = lane & 15;                 // A: matrices {rows0-7,8-15} x {k-chunk0,1}
    int achk = lane >> 4;
    int brow = (lane & 7) + ((lane >> 4) << 3);  // B: matrices {n0-7 kc0, n0-7 kc1, n8-15 kc0, n8-15 kc1}
    int bchk = (lane >> 3) & 1;

    float acc[4][4][4];
    #pragma unroll
    for (int a = 0; a < 4; a++)
        #pragma unroll
        for (int b = 0; b < 4; b++)
            #pragma unroll
            for (int c = 0; c < 4; c++) acc[a][b][c] = 0.f;

    const float4 Z = make_float4(0.f, 0.f, 0.f, 0.f);
    float4 pa0, pa1, pa2, pa3, pb0, pb1, pb2, pb3;
    // prefetch kt = 0
    pa0 = (!FUSED || aptr0) ? *(const float4*)(aptr0)     : Z;
    pa1 = (!FUSED || aptr0) ? *(const float4*)(aptr0 + 4) : Z;
    pa2 = (!FUSED || aptr1) ? *(const float4*)(aptr1)     : Z;
    pa3 = (!FUSED || aptr1) ? *(const float4*)(aptr1 + 4) : Z;
    pb0 = *(const float4*)(bptr0);     pb1 = *(const float4*)(bptr0 + 4);
    pb2 = *(const float4*)(bptr1);     pb3 = *(const float4*)(bptr1 + 4);

    #pragma unroll 1
    for (int kt = 0; kt < NK; kt++) {
        __syncthreads();
        {
            uint4 H, L;
            cvt8(pa0, pa1, H, L); STS128(SA_HI + off0, H); STS128(SA_LO + off0, L);
            cvt8(pa2, pa3, H, L); STS128(SA_HI + off1, H); STS128(SA_LO + off1, L);
            cvt8(pb0, pb1, H, L); STS128(SB_HI + off0, H); STS128(SB_LO + off0, L);
            cvt8(pb2, pb3, H, L); STS128(SB_HI + off1, H); STS128(SB_LO + off1, L);
        }
        if (kt + 1 < NK) {
            int ko = (kt + 1) * 32;
            pa0 = (!FUSED || aptr0) ? *(const float4*)(aptr0 + ko)     : Z;
            pa1 = (!FUSED || aptr0) ? *(const float4*)(aptr0 + ko + 4) : Z;
            pa2 = (!FUSED || aptr1) ? *(const float4*)(aptr1 + ko)     : Z;
            pa3 = (!FUSED || aptr1) ? *(const float4*)(aptr1 + ko + 4) : Z;
            pb0 = *(const float4*)(bptr0 + ko);     pb1 = *(const float4*)(bptr0 + ko + 4);
            pb2 = *(const float4*)(bptr1 + ko);     pb3 = *(const float4*)(bptr1 + ko + 4);
        }
        __syncthreads();

        #pragma unroll
        for (int kk = 0; kk < 2; kk++) {
            uint32_t aH[4][4], aL[4][4], bH[4][2], bL[4][2];
            #pragma unroll
            for (int mt = 0; mt < 4; mt++) {
                int row = wm * 64 + mt * 16 + arow;
                uint32_t ad = swz(row, 2 * kk + achk);
                ldsm_x4(aH[mt], SA_HI + ad);
                ldsm_x4(aL[mt], SA_LO + ad);
            }
            #pragma unroll
            for (int np = 0; np < 2; np++) {
                int row = wn * 32 + np * 16 + brow;
                uint32_t bd = swz(row, 2 * kk + bchk);
                uint32_t t4[4];
                ldsm_x4(t4, SB_HI + bd);                 // NON-trans: fragment = B[k][n]
                bH[2*np][0] = t4[0]; bH[2*np][1] = t4[1];
                bH[2*np+1][0] = t4[2]; bH[2*np+1][1] = t4[3];
                ldsm_x4(t4, SB_LO + bd);
                bL[2*np][0] = t4[0]; bL[2*np][1] = t4[1];
                bL[2*np+1][0] = t4[2]; bL[2*np+1][1] = t4[3];
            }
            #pragma unroll
            for (int mt = 0; mt < 4; mt++)
                #pragma unroll
                for (int nt = 0; nt < 4; nt++) {
                    mma16816(acc[mt][nt], aH[mt], bH[nt]);
                    mma16816(acc[mt][nt], aH[mt], bL[nt]);
                    mma16816(acc[mt][nt], aL[mt], bH[nt]);
                }
        }
    }
    __syncthreads();   // all frag reads done; sT reusable

    if (FUSED) {
        float* sUp = (float*)sT;   // [128][64] f32 = 32KB
        if (wn >= 2) {
            #pragma unroll
            for (int mt = 0; mt < 4; mt++)
                #pragma unroll
                for (int nt = 0; nt < 4; nt++) {
                    int m = wm * 64 + mt * 16 + (lane >> 2);
                    int c = (wn - 2) * 32 + nt * 8 + (lane & 3) * 2;
                    sUp[m * 64 + c]           = acc[mt][nt][0];
                    sUp[m * 64 + c + 1]       = acc[mt][nt][1];
                    sUp[(m + 8) * 64 + c]     = acc[mt][nt][2];
                    sUp[(m + 8) * 64 + c + 1] = acc[mt][nt][3];
                }
        }
        __syncthreads();
        if (wn < 2) {
            #pragma unroll
            for (int mt = 0; mt < 4; mt++)
                #pragma unroll
                for (int nt = 0; nt < 4; nt++) {
                    int m = wm * 64 + mt * 16 + (lane >> 2);
                    int c = wn * 32 + nt * 8 + (lane & 3) * 2;
                    #pragma unroll
                    for (int h = 0; h < 2; h++) {
                        int mm = m + h * 8;
                        float g0 = acc[mt][nt][h * 2], g1 = acc[mt][nt][h * 2 + 1];
                        float u0 = sUp[mm * 64 + c], u1 = sUp[mm * 64 + c + 1];
                        float2 o;
                        o.x = g0 / (1.f + expf(-g0)) * u0;
                        o.y = g1 / (1.f + expf(-g1)) * u1;
                        *(float2*)&g_inter[(size_t)(row0 + mm) * IDIM + nb * 64 + c] = o;
                    }
                }
        }
    } else {
        #pragma unroll
        for (int mt = 0; mt < 4; mt++)
            #pragma unroll
            for (int nt = 0; nt < 4; nt++) {
                int m = row0 + wm * 64 + mt * 16 + (lane >> 2);
                int c = nb * 128 + wn * 32 + nt * 8 + (lane & 3) * 2;
                *(float2*)&g_y2[(size_t)m * HID + c]       = make_float2(acc[mt][nt][0], acc[mt][nt][1]);
                *(float2*)&g_y2[(size_t)(m + 8) * HID + c] = make_float2(acc[mt][nt][2], acc[mt][nt][3]);
            }
    }
}

// ---------------- combine ----------------
__global__ void combine_kernel(float* __restrict__ out) {
    __shared__ float w[TOPK];
    __shared__ int rows[TOPK];
    int t = blockIdx.x;
    int tid = threadIdx.x;
    if (tid < TOPK) {
        w[tid]    = g_topkw[t * TOPK + tid];
        rows[tid] = g_invperm[t * TOPK + tid];
    }
    __syncthreads();
    float4 acc = make_float4(0.f, 0.f, 0.f, 0.f);
    #pragma unroll
    for (int k = 0; k < TOPK; k++) {
        const float4 v = *(const float4*)&g_y2[(size_t)rows[k] * HID + (tid << 2)];
        float wk = w[k];
        acc.x += wk * v.x; acc.y += wk * v.y; acc.z += wk * v.z; acc.w += wk * v.w;
    }
    *(float4*)(out + (size_t)t * HID + (tid << 2)) = acc;
}

// ---------------- launch ----------------
extern "C" void kernel_launch(void* const* d_in, const int* in_sizes, int n_in,
                              void* d_out, int out_size) {
    const float* x    = (const float*)d_in[0];
    const float* gate = (const float*)d_in[1];
    const float* gup  = (const float*)d_in[2];
    const float* dwn  = (const float*)d_in[3];
    float* out = (float*)d_out;

    init_kernel<<<1, 64>>>();
    router_kernel<<<NTOK / RT, 256>>>(x, gate);
    meta_kernel<<<1, 1>>>();
    fill_kernel<<<(MPAD + 255) / 256, 256>>>();
    scatter_kernel<<<(FLAT + 255) / 256, 256>>>();
    moe_gemm<true><<<dim3(MAXTILES, IDIM / 64), 256>>>(x, gup);
    moe_gemm<false><<<dim3(MAXTILES, HID / 128), 256>>>(nullptr, dwn);
    combine_kernel<<<NTOK, 256>>>(out);
}